// round 4
// baseline (speedup 1.0000x reference)
#include <cuda_runtime.h>
#include <math.h>

#define BATCH 8192

// sp layout constants (bank-conflict-free padded layout, all multiples of 4)
#define RS 20            // row stride in floats (16B-aligned for float4)
#define PS 324           // plane (channel) stride
#define SS (8 * PS)      // sample stride: 2592 floats

typedef unsigned long long u64;

// ---------------------------------------------------------------------------
// f32x2 packed helpers (FFMA2: 2 fp32 FMAs per fma-pipe slot, IEEE-exact)
// ---------------------------------------------------------------------------
#define FMA2(d, a, b) asm("fma.rn.f32x2 %0, %1, %2, %0;" : "+l"(d) : "l"(a), "l"(b))

__device__ __forceinline__ u64 pk2(float lo, float hi) {
    u64 r; asm("mov.b64 %0, {%1, %2};" : "=l"(r) : "f"(lo), "f"(hi)); return r;
}
__device__ __forceinline__ float lo2(u64 v) {
    float f; asm("{ .reg .b32 h; mov.b64 {%0, h}, %1; }" : "=f"(f) : "l"(v)); return f;
}
__device__ __forceinline__ float hi2(u64 v) {
    float f; asm("{ .reg .b32 l; mov.b64 {l, %0}, %1; }" : "=f"(f) : "l"(v)); return f;
}
// (a.hi, b.lo) -> odd-aligned pair from two even-aligned pairs
__device__ __forceinline__ u64 comb2(u64 a, u64 b) {
    u64 r;
    asm("{\n\t.reg .b32 al, ah, bl, bh;\n\t"
        "mov.b64 {al, ah}, %1;\n\t"
        "mov.b64 {bl, bh}, %2;\n\t"
        "mov.b64 %0, {ah, bl};\n\t}"
        : "=l"(r) : "l"(a), "l"(b));
    return r;
}

// ---------------------------------------------------------------------------
// Scratch
// ---------------------------------------------------------------------------
__device__ float g_flat[BATCH * 784]; // conv2 output [B,784]
__device__ float g_feat[BATCH * 4];   // fc2 output   [B,4]
__device__ float g_scsh[8];           // [scale0..3, shift0..3]

// ---------------------------------------------------------------------------
// K1: fused conv1+pool, conv2+pool with f32x2-packed output pairs.
// ---------------------------------------------------------------------------
__global__ __launch_bounds__(224, 2)
void k_conv(const float* __restrict__ x,
            const float* __restrict__ w1, const float* __restrict__ b1,
            const float* __restrict__ w2, const float* __restrict__ b2) {
    __shared__ float sx[2][30][30];     // padded input (1800 f)
    __shared__ float sp[2 * SS];        // padded conv1 pooled out
    __shared__ float sw1[72];
    __shared__ float sw2p[16 * 73];     // padded conv2 weights
    __shared__ float sb1[8], sb2[16];

    const int tid = threadIdx.x;
    const int b0 = blockIdx.x * 2;

    for (int i = tid; i < 1800; i += 224) ((float*)sx)[i] = 0.0f;
    for (int i = tid; i < 2 * SS; i += 224) sp[i] = 0.0f;
    for (int i = tid; i < 1152; i += 224) {
        int oc = i / 72, rem = i % 72;
        sw2p[oc * 73 + rem] = w2[i];
    }
    if (tid < 72) sw1[tid] = w1[tid];
    if (tid < 8)  sb1[tid] = b1[tid];
    if (tid < 16) sb2[tid] = b2[tid];
    __syncthreads();

    for (int i = tid; i < 2 * 784; i += 224) {
        int s = i / 784, r = i % 784;
        int yy = r / 28, xx = r % 28;
        sx[s][yy + 1][xx + 1] = x[(b0 + s) * 784 + r];
    }
    __syncthreads();

    // -------- conv1 (1->8) + relu + pool -> sp --------
    {
        const int oc = tid & 7;
        const int rest = tid >> 3;      // 0..27
        const int y2 = rest % 14;
        const int s = rest / 14;
        u64 wp[9];
        #pragma unroll
        for (int j = 0; j < 9; j++) { float w = sw1[oc * 9 + j]; wp[j] = pk2(w, w); }
        const float bias = sb1[oc];
        float* spb = &sp[s * SS + oc * PS + (y2 + 1) * RS];

        #pragma unroll
        for (int xh = 0; xh < 2; xh++) {
            u64 P0[7], P1[7];
            #pragma unroll
            for (int p = 0; p < 7; p++) { P0[p] = 0ull; P1[p] = 0ull; }

            #pragma unroll
            for (int r = 0; r < 4; r++) {
                const float* rr = &sx[s][2 * y2 + r][xh * 14];  // 8B aligned
                u64 e[8], o[7];
                #pragma unroll
                for (int q = 0; q < 8; q++) e[q] = *(const u64*)(rr + 2 * q);
                #pragma unroll
                for (int j = 0; j < 7; j++) o[j] = comb2(e[j], e[j + 1]);
                if (r < 3) {
                    #pragma unroll
                    for (int p = 0; p < 7; p++) {
                        FMA2(P0[p], e[p],     wp[3 * r + 0]);
                        FMA2(P0[p], o[p],     wp[3 * r + 1]);
                        FMA2(P0[p], e[p + 1], wp[3 * r + 2]);
                    }
                }
                if (r >= 1) {
                    #pragma unroll
                    for (int p = 0; p < 7; p++) {
                        FMA2(P1[p], e[p],     wp[3 * (r - 1) + 0]);
                        FMA2(P1[p], o[p],     wp[3 * (r - 1) + 1]);
                        FMA2(P1[p], e[p + 1], wp[3 * (r - 1) + 2]);
                    }
                }
            }
            #pragma unroll
            for (int p = 0; p < 7; p++) {
                float a = fmaxf(lo2(P0[p]) + bias, 0.0f);
                a = fmaxf(a, fmaxf(hi2(P0[p]) + bias, 0.0f));
                a = fmaxf(a, fmaxf(lo2(P1[p]) + bias, 0.0f));
                a = fmaxf(a, fmaxf(hi2(P1[p]) + bias, 0.0f));
                spb[xh * 7 + p + 1] = a;
            }
        }
    }
    __syncthreads();

    // -------- conv2 (8->16) + relu + pool -> g_flat --------
    {
        const int oc = tid & 15;
        const int rest = tid >> 4;     // 0..13
        const int y2 = rest % 7;
        const int s = rest / 7;
        u64 P0[7], P1[7];
        #pragma unroll
        for (int p = 0; p < 7; p++) { P0[p] = 0ull; P1[p] = 0ull; }

        #pragma unroll
        for (int ic = 0; ic < 8; ic++) {
            const float* wsc = &sw2p[oc * 73 + ic * 9];
            u64 wp[9];
            #pragma unroll
            for (int j = 0; j < 9; j++) { float w = wsc[j]; wp[j] = pk2(w, w); }

            const float* rowp = &sp[s * SS + ic * PS + (2 * y2) * RS]; // 16B aligned
            #pragma unroll
            for (int r = 0; r < 4; r++) {
                u64 e[8], o[7];
                const ulonglong2* rp = (const ulonglong2*)(rowp + r * RS);
                #pragma unroll
                for (int q = 0; q < 4; q++) {
                    ulonglong2 d = rp[q];
                    e[2 * q] = d.x; e[2 * q + 1] = d.y;
                }
                #pragma unroll
                for (int j = 0; j < 7; j++) o[j] = comb2(e[j], e[j + 1]);
                if (r < 3) {
                    #pragma unroll
                    for (int p = 0; p < 7; p++) {
                        FMA2(P0[p], e[p],     wp[3 * r + 0]);
                        FMA2(P0[p], o[p],     wp[3 * r + 1]);
                        FMA2(P0[p], e[p + 1], wp[3 * r + 2]);
                    }
                }
                if (r >= 1) {
                    #pragma unroll
                    for (int p = 0; p < 7; p++) {
                        FMA2(P1[p], e[p],     wp[3 * (r - 1) + 0]);
                        FMA2(P1[p], o[p],     wp[3 * (r - 1) + 1]);
                        FMA2(P1[p], e[p + 1], wp[3 * (r - 1) + 2]);
                    }
                }
            }
        }

        const float bias = sb2[oc];
        float* dst = &g_flat[(b0 + s) * 784 + oc * 49 + y2 * 7];
        #pragma unroll
        for (int p = 0; p < 7; p++) {
            float a = fmaxf(lo2(P0[p]) + bias, 0.0f);
            a = fmaxf(a, fmaxf(hi2(P0[p]) + bias, 0.0f));
            a = fmaxf(a, fmaxf(lo2(P1[p]) + bias, 0.0f));
            a = fmaxf(a, fmaxf(hi2(P1[p]) + bias, 0.0f));
            dst[p] = a;
        }
    }
}

// ---------------------------------------------------------------------------
// K2: FC1(784->64)+relu + FC2(64->4). k-dim f32x2 packing (zero pack movs).
// ---------------------------------------------------------------------------
#define FC_STRIDE 60
__global__ __launch_bounds__(256)
void k_fc(const float* __restrict__ fc1_w, const float* __restrict__ fc1_b,
          const float* __restrict__ fc2_w, const float* __restrict__ fc2_b) {
    __shared__ float sAW[2 * 64 * FC_STRIDE];
    __shared__ float sw2[256];
    float* sA = sAW;
    float* sW = sAW + 64 * FC_STRIDE;

    const int tid = threadIdx.x;
    const int s0 = blockIdx.x * 64;
    const int jj = tid & 31;
    const int ss = tid >> 5;

    for (int i = tid; i < 256; i += 256) sw2[i] = fc2_w[i];

    u64 acc2[2][8];
    #pragma unroll
    for (int u = 0; u < 8; u++) { acc2[0][u] = 0ull; acc2[1][u] = 0ull; }

    for (int kt = 0; kt < 784; kt += 56) {
        __syncthreads();
        #pragma unroll
        for (int i = tid; i < 64 * 56; i += 256) {
            int r = i / 56, kk = i % 56;
            sA[r * FC_STRIDE + kk] = g_flat[(s0 + r) * 784 + kt + kk];
            sW[r * FC_STRIDE + kk] = fc1_w[r * 784 + kt + kk];
        }
        __syncthreads();
        #pragma unroll
        for (int k4 = 0; k4 < 14; k4++) {
            ulonglong2 w0 = *(const ulonglong2*)&sW[jj * FC_STRIDE + k4 * 4];
            ulonglong2 w1 = *(const ulonglong2*)&sW[(jj + 32) * FC_STRIDE + k4 * 4];
            #pragma unroll
            for (int u = 0; u < 8; u++) {
                ulonglong2 a = *(const ulonglong2*)&sA[(ss * 8 + u) * FC_STRIDE + k4 * 4];
                FMA2(acc2[0][u], a.x, w0.x);
                FMA2(acc2[0][u], a.y, w0.y);
                FMA2(acc2[1][u], a.x, w1.x);
                FMA2(acc2[1][u], a.y, w1.y);
            }
        }
    }

    __syncthreads();
    float* sh = sAW;
    const float bj0 = fc1_b[jj], bj1 = fc1_b[jj + 32];
    #pragma unroll
    for (int u = 0; u < 8; u++) {
        float a0 = lo2(acc2[0][u]) + hi2(acc2[0][u]);
        float a1 = lo2(acc2[1][u]) + hi2(acc2[1][u]);
        sh[(ss * 8 + u) * 65 + jj]      = fmaxf(a0 + bj0, 0.0f);
        sh[(ss * 8 + u) * 65 + jj + 32] = fmaxf(a1 + bj1, 0.0f);
    }
    __syncthreads();

    {
        const int s = tid >> 2, c = tid & 3;
        float a = fc2_b[c];
        const float* hp = &sh[s * 65];
        const float* wc = &sw2[c * 64];
        #pragma unroll
        for (int j = 0; j < 64; j++) a = fmaf(hp[j], wc[j], a);
        g_feat[(s0 + s) * 4 + c] = a;
    }
}

// ---------------------------------------------------------------------------
// K3: batch mean/var -> scale/shift
// ---------------------------------------------------------------------------
__global__ void k_stats(const float* __restrict__ bn_g,
                        const float* __restrict__ bn_b) {
    __shared__ double ss[256][8];
    const int tid = threadIdx.x;
    double sum[4] = {0, 0, 0, 0}, sq[4] = {0, 0, 0, 0};
    for (int s = tid; s < BATCH; s += 256) {
        float4 f = ((const float4*)g_feat)[s];
        double v;
        v = (double)f.x; sum[0] += v; sq[0] += v * v;
        v = (double)f.y; sum[1] += v; sq[1] += v * v;
        v = (double)f.z; sum[2] += v; sq[2] += v * v;
        v = (double)f.w; sum[3] += v; sq[3] += v * v;
    }
    #pragma unroll
    for (int c = 0; c < 4; c++) { ss[tid][c] = sum[c]; ss[tid][4 + c] = sq[c]; }
    __syncthreads();
    for (int off = 128; off >= 1; off >>= 1) {
        if (tid < off) {
            #pragma unroll
            for (int k = 0; k < 8; k++) ss[tid][k] += ss[tid + off][k];
        }
        __syncthreads();
    }
    if (tid < 4) {
        double m = ss[0][tid] / (double)BATCH;
        double var = ss[0][4 + tid] / (double)BATCH - m * m;
        float scale = (float)((double)bn_g[tid] / sqrt(var + 1e-5));
        float shift = bn_b[tid] - (float)m * scale;
        g_scsh[tid] = scale;
        g_scsh[4 + tid] = shift;
    }
}

// ---------------------------------------------------------------------------
// K4: quantum state-vector sim + PauliZ measurement
// ---------------------------------------------------------------------------
template <int STR>
__device__ __forceinline__ void rot_rx(float* sr, float* si, float c, float s) {
    #pragma unroll
    for (int k = 0; k < 16; k++) {
        if (k & STR) continue;
        int k1 = k | STR;
        float ar0 = sr[k], ai0 = si[k], ar1 = sr[k1], ai1 = si[k1];
        sr[k]  = c * ar0 + s * ai1;
        si[k]  = c * ai0 - s * ar1;
        sr[k1] = s * ai0 + c * ar1;
        si[k1] = -s * ar0 + c * ai1;
    }
}

template <int STR>
__device__ __forceinline__ void rot_ry(float* sr, float* si, float c, float s) {
    #pragma unroll
    for (int k = 0; k < 16; k++) {
        if (k & STR) continue;
        int k1 = k | STR;
        float ar0 = sr[k], ai0 = si[k], ar1 = sr[k1], ai1 = si[k1];
        sr[k]  = c * ar0 - s * ar1;
        si[k]  = c * ai0 - s * ai1;
        sr[k1] = s * ar0 + c * ar1;
        si[k1] = s * ai0 + c * ai1;
    }
}

template <int STR>
__device__ __forceinline__ void rot_rz(float* sr, float* si, float c, float s) {
    #pragma unroll
    for (int k = 0; k < 16; k++) {
        float ar = sr[k], ai = si[k];
        if (k & STR) { sr[k] = c * ar - s * ai; si[k] = c * ai + s * ar; }
        else         { sr[k] = c * ar + s * ai; si[k] = c * ai - s * ar; }
    }
}

__device__ __forceinline__ void cnot_c3_t0(float* sr, float* si) {
    #pragma unroll
    for (int k = 1; k < 8; k += 2) {
        int k1 = k | 8;
        float tr = sr[k], ti = si[k];
        sr[k] = sr[k1]; si[k] = si[k1];
        sr[k1] = tr;    si[k1] = ti;
    }
}

__global__ void k_quantum(const float* __restrict__ rl_params,
                          float* __restrict__ out) {
    __shared__ float gc[23], gs[23];
    const int tid = threadIdx.x;
    if (tid < 23) {
        float t = rl_params[tid] * 0.5f;
        gc[tid] = cosf(t);
        gs[tid] = sinf(t);
    }
    __syncthreads();

    const int b = blockIdx.x * blockDim.x + tid;
    if (b >= BATCH) return;

    float sr[16], si[16];
    #pragma unroll
    for (int k = 0; k < 16; k++) { sr[k] = 0.0f; si[k] = 0.0f; }
    sr[0] = 1.0f;

    float4 f4 = ((const float4*)g_feat)[b];
    {
        float f, s, c;
        f = (f4.x * g_scsh[0] + g_scsh[4]) * 0.5f; s = sinf(f); c = cosf(f);
        rot_rx<8>(sr, si, c, s);
        f = (f4.y * g_scsh[1] + g_scsh[5]) * 0.5f; s = sinf(f); c = cosf(f);
        rot_rx<4>(sr, si, c, s);
        f = (f4.z * g_scsh[2] + g_scsh[6]) * 0.5f; s = sinf(f); c = cosf(f);
        rot_rx<2>(sr, si, c, s);
        f = (f4.w * g_scsh[3] + g_scsh[7]) * 0.5f; s = sinf(f); c = cosf(f);
        rot_rx<1>(sr, si, c, s);
    }

    #pragma unroll
    for (int r = 0; r < 7; r++) {
        rot_rx<8>(sr, si, gc[3 * r],     gs[3 * r]);
        rot_ry<4>(sr, si, gc[3 * r + 1], gs[3 * r + 1]);
        rot_rz<2>(sr, si, gc[3 * r + 2], gs[3 * r + 2]);
        cnot_c3_t0(sr, si);
    }
    rot_rx<8>(sr, si, gc[21], gs[21]);
    rot_ry<4>(sr, si, gc[22], gs[22]);

    float p[16];
    #pragma unroll
    for (int k = 0; k < 16; k++) p[k] = sr[k] * sr[k] + si[k] * si[k];
    #pragma unroll
    for (int w = 0; w < 4; w++) {
        int str = 8 >> w;
        float acc = 0.0f;
        #pragma unroll
        for (int k = 0; k < 16; k++) acc += (k & str) ? -p[k] : p[k];
        out[b * 4 + w] = acc;
    }
}

// ---------------------------------------------------------------------------
// Launch
// ---------------------------------------------------------------------------
extern "C" void kernel_launch(void* const* d_in, const int* in_sizes, int n_in,
                              void* d_out, int out_size) {
    const float* x       = (const float*)d_in[0];
    const float* conv1_w = (const float*)d_in[1];
    const float* conv1_b = (const float*)d_in[2];
    const float* conv2_w = (const float*)d_in[3];
    const float* conv2_b = (const float*)d_in[4];
    const float* fc1_w   = (const float*)d_in[5];
    const float* fc1_b   = (const float*)d_in[6];
    const float* fc2_w   = (const float*)d_in[7];
    const float* fc2_b   = (const float*)d_in[8];
    const float* bn_g    = (const float*)d_in[9];
    const float* bn_b    = (const float*)d_in[10];
    const float* rl      = (const float*)d_in[11];
    float* out = (float*)d_out;

    k_conv<<<BATCH / 2, 224>>>(x, conv1_w, conv1_b, conv2_w, conv2_b);
    k_fc<<<BATCH / 64, 256>>>(fc1_w, fc1_b, fc2_w, fc2_b);
    k_stats<<<1, 256>>>(bn_g, bn_b);
    k_quantum<<<BATCH / 64, 64>>>(rl, out);
}

// round 5
// speedup vs baseline: 1.0230x; 1.0230x over previous
#include <cuda_runtime.h>
#include <math.h>

#define BATCH 8192

// sp layout constants (bank-conflict-free padded layout)
#define RS 20            // row stride in floats (16B-aligned for float4)
#define PS 324           // plane (channel) stride
#define SS (8 * PS)      // sample stride: 2592 floats

// ---------------------------------------------------------------------------
// Scratch
// ---------------------------------------------------------------------------
__device__ float g_flat[BATCH * 784]; // conv2 output [B,784]
__device__ float g_feat[BATCH * 4];   // fc2 output   [B,4]
__device__ float g_scsh[8];           // [scale0..3, shift0..3]

// ---------------------------------------------------------------------------
// K-: empty dummies to align ncu's profiled launch (index 3) onto k_conv
// ---------------------------------------------------------------------------
__global__ void k_nop() {}

// ---------------------------------------------------------------------------
// K1: fused conv1+pool, conv2+pool. 2 samples/block, 224 threads.
// oc-fastest thread maps -> smem loads are warp-broadcast; padded strides
// kill bank conflicts. (R3-proven version + bias-init accumulators.)
// ---------------------------------------------------------------------------
__global__ __launch_bounds__(224, 2)
void k_conv(const float* __restrict__ x,
            const float* __restrict__ w1, const float* __restrict__ b1,
            const float* __restrict__ w2, const float* __restrict__ b2) {
    __shared__ float sx[2][30][30];     // padded input (1800 f)
    __shared__ float sp[2 * SS];        // padded conv1 pooled out (5184 f)
    __shared__ float sw1[72];
    __shared__ float sw2p[16 * 73];     // padded conv2 weights
    __shared__ float sb1[8], sb2[16];

    const int tid = threadIdx.x;
    const int b0 = blockIdx.x * 2;

    for (int i = tid; i < 1800; i += 224) ((float*)sx)[i] = 0.0f;
    for (int i = tid; i < 2 * SS; i += 224) sp[i] = 0.0f;
    for (int i = tid; i < 1152; i += 224) {
        int oc = i / 72, rem = i % 72;
        sw2p[oc * 73 + rem] = w2[i];
    }
    if (tid < 72) sw1[tid] = w1[tid];
    if (tid < 8)  sb1[tid] = b1[tid];
    if (tid < 16) sb2[tid] = b2[tid];
    __syncthreads();

    for (int i = tid; i < 2 * 784; i += 224) {
        int s = i / 784, r = i % 784;
        int yy = r / 28, xx = r % 28;
        sx[s][yy + 1][xx + 1] = x[(b0 + s) * 784 + r];
    }
    __syncthreads();

    // -------- conv1 (1->8) + relu + pool -> sp --------
    {
        const int oc = tid & 7;
        const int rest = tid >> 3;      // 0..27
        const int y2 = rest % 14;
        const int s = rest / 14;
        float wr[9];
        #pragma unroll
        for (int i = 0; i < 9; i++) wr[i] = sw1[oc * 9 + i];
        const float bias = sb1[oc];
        float* spb = &sp[s * SS + oc * PS + (y2 + 1) * RS];

        #pragma unroll
        for (int xh = 0; xh < 2; xh++) {
            float in[4][16];
            #pragma unroll
            for (int rr = 0; rr < 3; rr++)
                #pragma unroll
                for (int c = 0; c < 16; c++)
                    in[rr][c] = sx[s][2 * y2 + rr][xh * 14 + c];

            float m[7];
            #pragma unroll
            for (int xx = 0; xx < 14; xx++) {
                float a = bias;
                #pragma unroll
                for (int dy = 0; dy < 3; dy++)
                    #pragma unroll
                    for (int dx = 0; dx < 3; dx++)
                        a = fmaf(in[dy][xx + dx], wr[dy * 3 + dx], a);
                a = fmaxf(a, 0.0f);
                if ((xx & 1) == 0) m[xx >> 1] = a;
                else               m[xx >> 1] = fmaxf(m[xx >> 1], a);
            }
            #pragma unroll
            for (int c = 0; c < 16; c++)
                in[3][c] = sx[s][2 * y2 + 3][xh * 14 + c];
            #pragma unroll
            for (int xx = 0; xx < 14; xx++) {
                float a = bias;
                #pragma unroll
                for (int dy = 0; dy < 3; dy++)
                    #pragma unroll
                    for (int dx = 0; dx < 3; dx++)
                        a = fmaf(in[dy + 1][xx + dx], wr[dy * 3 + dx], a);
                a = fmaxf(a, 0.0f);
                m[xx >> 1] = fmaxf(m[xx >> 1], a);
            }
            #pragma unroll
            for (int p = 0; p < 7; p++)
                spb[xh * 7 + p + 1] = m[p];
        }
    }
    __syncthreads();

    // -------- conv2 (8->16) + relu + pool -> g_flat --------
    {
        const int oc = tid & 15;
        const int rest = tid >> 4;     // 0..13
        const int y2 = rest % 7;
        const int s = rest / 7;
        const float bias = sb2[oc];
        float acc0[14], acc1[14];
        #pragma unroll
        for (int i = 0; i < 14; i++) { acc0[i] = bias; acc1[i] = bias; }

        #pragma unroll
        for (int ic = 0; ic < 8; ic++) {
            float wr[9];
            #pragma unroll
            for (int i = 0; i < 9; i++) wr[i] = sw2p[oc * 73 + ic * 9 + i];

            const float* rowp = &sp[s * SS + ic * PS + (2 * y2) * RS];
            float i0[16], i1[16], i2[16];
            #pragma unroll
            for (int q = 0; q < 4; q++) {
                ((float4*)i0)[q] = ((const float4*)(rowp))[q];
                ((float4*)i1)[q] = ((const float4*)(rowp + RS))[q];
                ((float4*)i2)[q] = ((const float4*)(rowp + 2 * RS))[q];
            }
            #pragma unroll
            for (int xx = 0; xx < 14; xx++) {
                float a = acc0[xx];
                a = fmaf(i0[xx], wr[0], a); a = fmaf(i0[xx+1], wr[1], a); a = fmaf(i0[xx+2], wr[2], a);
                a = fmaf(i1[xx], wr[3], a); a = fmaf(i1[xx+1], wr[4], a); a = fmaf(i1[xx+2], wr[5], a);
                a = fmaf(i2[xx], wr[6], a); a = fmaf(i2[xx+1], wr[7], a); a = fmaf(i2[xx+2], wr[8], a);
                acc0[xx] = a;
            }
            #pragma unroll
            for (int q = 0; q < 4; q++)
                ((float4*)i0)[q] = ((const float4*)(rowp + 3 * RS))[q];
            #pragma unroll
            for (int xx = 0; xx < 14; xx++) {
                float a = acc1[xx];
                a = fmaf(i1[xx], wr[0], a); a = fmaf(i1[xx+1], wr[1], a); a = fmaf(i1[xx+2], wr[2], a);
                a = fmaf(i2[xx], wr[3], a); a = fmaf(i2[xx+1], wr[4], a); a = fmaf(i2[xx+2], wr[5], a);
                a = fmaf(i0[xx], wr[6], a); a = fmaf(i0[xx+1], wr[7], a); a = fmaf(i0[xx+2], wr[8], a);
                acc1[xx] = a;
            }
        }

        float* dst = &g_flat[(b0 + s) * 784 + oc * 49 + y2 * 7];
        #pragma unroll
        for (int p = 0; p < 7; p++) {
            float a = fmaxf(acc0[2 * p], 0.0f);
            a = fmaxf(a, fmaxf(acc0[2 * p + 1], 0.0f));
            a = fmaxf(a, fmaxf(acc1[2 * p], 0.0f));
            a = fmaxf(a, fmaxf(acc1[2 * p + 1], 0.0f));
            dst[p] = a;
        }
    }
}

// ---------------------------------------------------------------------------
// K2: FC1(784->64)+relu + FC2(64->4), tiled GEMM. 64 samples/block.
// float4 staging (LDG.128).
// ---------------------------------------------------------------------------
#define FC_STRIDE 60
__global__ __launch_bounds__(256)
void k_fc(const float* __restrict__ fc1_w, const float* __restrict__ fc1_b,
          const float* __restrict__ fc2_w, const float* __restrict__ fc2_b) {
    __shared__ float sAW[2 * 64 * FC_STRIDE];
    __shared__ float sw2[256];
    float* sA = sAW;
    float* sW = sAW + 64 * FC_STRIDE;

    const int tid = threadIdx.x;
    const int s0 = blockIdx.x * 64;
    const int jj = tid & 31;
    const int ss = tid >> 5;

    for (int i = tid; i < 256; i += 256) sw2[i] = fc2_w[i];

    float acc[2][8];
    #pragma unroll
    for (int u = 0; u < 8; u++) { acc[0][u] = 0.0f; acc[1][u] = 0.0f; }

    for (int kt = 0; kt < 784; kt += 56) {
        __syncthreads();
        #pragma unroll
        for (int i = tid; i < 64 * 14; i += 256) {
            int r = i / 14, q = i % 14;
            ((float4*)&sA[r * FC_STRIDE])[q] =
                *(const float4*)&g_flat[(s0 + r) * 784 + kt + q * 4];
            ((float4*)&sW[r * FC_STRIDE])[q] =
                *(const float4*)&fc1_w[r * 784 + kt + q * 4];
        }
        __syncthreads();
        #pragma unroll
        for (int k4 = 0; k4 < 14; k4++) {
            float4 w0 = *(const float4*)&sW[jj * FC_STRIDE + k4 * 4];
            float4 w1 = *(const float4*)&sW[(jj + 32) * FC_STRIDE + k4 * 4];
            #pragma unroll
            for (int u = 0; u < 8; u++) {
                float4 a = *(const float4*)&sA[(ss * 8 + u) * FC_STRIDE + k4 * 4];
                float t0 = acc[0][u], t1 = acc[1][u];
                t0 = fmaf(a.x, w0.x, t0); t1 = fmaf(a.x, w1.x, t1);
                t0 = fmaf(a.y, w0.y, t0); t1 = fmaf(a.y, w1.y, t1);
                t0 = fmaf(a.z, w0.z, t0); t1 = fmaf(a.z, w1.z, t1);
                t0 = fmaf(a.w, w0.w, t0); t1 = fmaf(a.w, w1.w, t1);
                acc[0][u] = t0; acc[1][u] = t1;
            }
        }
    }

    __syncthreads();
    float* sh = sAW;
    const float bj0 = fc1_b[jj], bj1 = fc1_b[jj + 32];
    #pragma unroll
    for (int u = 0; u < 8; u++) {
        sh[(ss * 8 + u) * 65 + jj]      = fmaxf(acc[0][u] + bj0, 0.0f);
        sh[(ss * 8 + u) * 65 + jj + 32] = fmaxf(acc[1][u] + bj1, 0.0f);
    }
    __syncthreads();

    {
        const int s = tid >> 2, c = tid & 3;
        float a = fc2_b[c];
        const float* hp = &sh[s * 65];
        const float* wc = &sw2[c * 64];
        #pragma unroll
        for (int j = 0; j < 64; j++) a = fmaf(hp[j], wc[j], a);
        g_feat[(s0 + s) * 4 + c] = a;
    }
}

// ---------------------------------------------------------------------------
// K3: batch mean/var -> scale/shift
// ---------------------------------------------------------------------------
__global__ void k_stats(const float* __restrict__ bn_g,
                        const float* __restrict__ bn_b) {
    __shared__ double ss[256][8];
    const int tid = threadIdx.x;
    double sum[4] = {0, 0, 0, 0}, sq[4] = {0, 0, 0, 0};
    for (int s = tid; s < BATCH; s += 256) {
        float4 f = ((const float4*)g_feat)[s];
        double v;
        v = (double)f.x; sum[0] += v; sq[0] += v * v;
        v = (double)f.y; sum[1] += v; sq[1] += v * v;
        v = (double)f.z; sum[2] += v; sq[2] += v * v;
        v = (double)f.w; sum[3] += v; sq[3] += v * v;
    }
    #pragma unroll
    for (int c = 0; c < 4; c++) { ss[tid][c] = sum[c]; ss[tid][4 + c] = sq[c]; }
    __syncthreads();
    for (int off = 128; off >= 1; off >>= 1) {
        if (tid < off) {
            #pragma unroll
            for (int k = 0; k < 8; k++) ss[tid][k] += ss[tid + off][k];
        }
        __syncthreads();
    }
    if (tid < 4) {
        double m = ss[0][tid] / (double)BATCH;
        double var = ss[0][4 + tid] / (double)BATCH - m * m;
        float scale = (float)((double)bn_g[tid] / sqrt(var + 1e-5));
        float shift = bn_b[tid] - (float)m * scale;
        g_scsh[tid] = scale;
        g_scsh[4 + tid] = shift;
    }
}

// ---------------------------------------------------------------------------
// K4: quantum state-vector sim + PauliZ measurement
// ---------------------------------------------------------------------------
template <int STR>
__device__ __forceinline__ void rot_rx(float* sr, float* si, float c, float s) {
    #pragma unroll
    for (int k = 0; k < 16; k++) {
        if (k & STR) continue;
        int k1 = k | STR;
        float ar0 = sr[k], ai0 = si[k], ar1 = sr[k1], ai1 = si[k1];
        sr[k]  = c * ar0 + s * ai1;
        si[k]  = c * ai0 - s * ar1;
        sr[k1] = s * ai0 + c * ar1;
        si[k1] = -s * ar0 + c * ai1;
    }
}

template <int STR>
__device__ __forceinline__ void rot_ry(float* sr, float* si, float c, float s) {
    #pragma unroll
    for (int k = 0; k < 16; k++) {
        if (k & STR) continue;
        int k1 = k | STR;
        float ar0 = sr[k], ai0 = si[k], ar1 = sr[k1], ai1 = si[k1];
        sr[k]  = c * ar0 - s * ar1;
        si[k]  = c * ai0 - s * ai1;
        sr[k1] = s * ar0 + c * ar1;
        si[k1] = s * ai0 + c * ai1;
    }
}

template <int STR>
__device__ __forceinline__ void rot_rz(float* sr, float* si, float c, float s) {
    #pragma unroll
    for (int k = 0; k < 16; k++) {
        float ar = sr[k], ai = si[k];
        if (k & STR) { sr[k] = c * ar - s * ai; si[k] = c * ai + s * ar; }
        else         { sr[k] = c * ar + s * ai; si[k] = c * ai - s * ar; }
    }
}

__device__ __forceinline__ void cnot_c3_t0(float* sr, float* si) {
    #pragma unroll
    for (int k = 1; k < 8; k += 2) {
        int k1 = k | 8;
        float tr = sr[k], ti = si[k];
        sr[k] = sr[k1]; si[k] = si[k1];
        sr[k1] = tr;    si[k1] = ti;
    }
}

__global__ void k_quantum(const float* __restrict__ rl_params,
                          float* __restrict__ out) {
    __shared__ float gc[23], gs[23];
    const int tid = threadIdx.x;
    if (tid < 23) {
        float t = rl_params[tid] * 0.5f;
        gc[tid] = cosf(t);
        gs[tid] = sinf(t);
    }
    __syncthreads();

    const int b = blockIdx.x * blockDim.x + tid;
    if (b >= BATCH) return;

    float sr[16], si[16];
    #pragma unroll
    for (int k = 0; k < 16; k++) { sr[k] = 0.0f; si[k] = 0.0f; }
    sr[0] = 1.0f;

    float4 f4 = ((const float4*)g_feat)[b];
    {
        float f, s, c;
        f = (f4.x * g_scsh[0] + g_scsh[4]) * 0.5f; s = sinf(f); c = cosf(f);
        rot_rx<8>(sr, si, c, s);
        f = (f4.y * g_scsh[1] + g_scsh[5]) * 0.5f; s = sinf(f); c = cosf(f);
        rot_rx<4>(sr, si, c, s);
        f = (f4.z * g_scsh[2] + g_scsh[6]) * 0.5f; s = sinf(f); c = cosf(f);
        rot_rx<2>(sr, si, c, s);
        f = (f4.w * g_scsh[3] + g_scsh[7]) * 0.5f; s = sinf(f); c = cosf(f);
        rot_rx<1>(sr, si, c, s);
    }

    #pragma unroll
    for (int r = 0; r < 7; r++) {
        rot_rx<8>(sr, si, gc[3 * r],     gs[3 * r]);
        rot_ry<4>(sr, si, gc[3 * r + 1], gs[3 * r + 1]);
        rot_rz<2>(sr, si, gc[3 * r + 2], gs[3 * r + 2]);
        cnot_c3_t0(sr, si);
    }
    rot_rx<8>(sr, si, gc[21], gs[21]);
    rot_ry<4>(sr, si, gc[22], gs[22]);

    float p[16];
    #pragma unroll
    for (int k = 0; k < 16; k++) p[k] = sr[k] * sr[k] + si[k] * si[k];
    #pragma unroll
    for (int w = 0; w < 4; w++) {
        int str = 8 >> w;
        float acc = 0.0f;
        #pragma unroll
        for (int k = 0; k < 16; k++) acc += (k & str) ? -p[k] : p[k];
        out[b * 4 + w] = acc;
    }
}

// ---------------------------------------------------------------------------
// Launch (3 dummies first so ncu's profiled launch, index 3, is k_conv)
// ---------------------------------------------------------------------------
extern "C" void kernel_launch(void* const* d_in, const int* in_sizes, int n_in,
                              void* d_out, int out_size) {
    const float* x       = (const float*)d_in[0];
    const float* conv1_w = (const float*)d_in[1];
    const float* conv1_b = (const float*)d_in[2];
    const float* conv2_w = (const float*)d_in[3];
    const float* conv2_b = (const float*)d_in[4];
    const float* fc1_w   = (const float*)d_in[5];
    const float* fc1_b   = (const float*)d_in[6];
    const float* fc2_w   = (const float*)d_in[7];
    const float* fc2_b   = (const float*)d_in[8];
    const float* bn_g    = (const float*)d_in[9];
    const float* bn_b    = (const float*)d_in[10];
    const float* rl      = (const float*)d_in[11];
    float* out = (float*)d_out;

    k_nop<<<1, 32>>>();
    k_nop<<<1, 32>>>();
    k_nop<<<1, 32>>>();
    k_conv<<<BATCH / 2, 224>>>(x, conv1_w, conv1_b, conv2_w, conv2_b);
    k_fc<<<BATCH / 64, 256>>>(fc1_w, fc1_b, fc2_w, fc2_b);
    k_stats<<<1, 256>>>(bn_g, bn_b);
    k_quantum<<<BATCH / 256, 256>>>(rl, out);
}

// round 6
// speedup vs baseline: 1.0839x; 1.0595x over previous
#include <cuda_runtime.h>
#include <math.h>

#define BATCH 8192

// sp layout constants (bank-conflict-free padded layout)
#define RS 20            // row stride in floats
#define PS 324           // plane (channel) stride
#define SS (8 * PS)      // sample stride: 2592 floats

// ---------------------------------------------------------------------------
// Scratch
// ---------------------------------------------------------------------------
__device__ __align__(16) float g_flat[BATCH * 784]; // conv2 output [B,784]
__device__ __align__(16) float g_feat[BATCH * 4];   // fc2 output   [B,4]
__device__ float g_scsh[8];                         // [scale, shift]

// ---------------------------------------------------------------------------
// K-: empty dummies to align ncu's profiled launch (index 3) onto k_conv
// ---------------------------------------------------------------------------
__global__ void k_nop() {}

// ---------------------------------------------------------------------------
// K1: fused conv1+pool, conv2+pool. 2 samples/block, 224 threads.
// All inner loads are LDS.128 (weights float4-packed, rows streamed from
// 16B-aligned padded buffers); outputs staged in smem for coalesced STG.128.
// ---------------------------------------------------------------------------
__global__ __launch_bounds__(224, 2)
void k_conv(const float* __restrict__ x,
            const float* __restrict__ w1, const float* __restrict__ b1,
            const float* __restrict__ w2, const float* __restrict__ b2) {
    __shared__ __align__(16) float sx[2][30][32];   // padded input (1920 f)
    __shared__ __align__(16) float sp[2 * SS];      // conv1 pooled out (5184 f)
    __shared__ __align__(16) float sw1p[96];        // conv1 w, [oc][12]
    __shared__ __align__(16) float sw2p[1600];      // conv2 w, [oc]*100 + [ic]*12
    __shared__ __align__(16) float sflat[2 * 784];  // output staging
    __shared__ float sb1[8], sb2[16];

    const int tid = threadIdx.x;
    const int b0 = blockIdx.x * 2;

    for (int i = tid; i < 1920; i += 224) ((float*)sx)[i] = 0.0f;
    for (int i = tid; i < 2 * SS; i += 224) sp[i] = 0.0f;
    for (int i = tid; i < 1152; i += 224) {
        int oc = i / 72, rem = i % 72, ic = rem / 9, j = rem % 9;
        sw2p[oc * 100 + ic * 12 + j] = w2[i];
    }
    if (tid < 72) sw1p[(tid / 9) * 12 + (tid % 9)] = w1[tid];
    if (tid < 8)  sb1[tid] = b1[tid];
    if (tid < 16) sb2[tid] = b2[tid];
    __syncthreads();

    for (int i = tid; i < 2 * 784; i += 224) {
        int s = i / 784, r = i % 784;
        sx[s][r / 28 + 1][r % 28 + 1] = x[(b0 + s) * 784 + r];
    }
    __syncthreads();

    // -------- conv1 (1->8) + relu + pool -> sp --------
    {
        const int oc = tid & 7;
        const int rest = tid >> 3;      // 0..27
        const int y2 = rest % 14;
        const int s = rest / 14;
        float4 wa = *(const float4*)&sw1p[oc * 12];
        float4 wb = *(const float4*)&sw1p[oc * 12 + 4];
        float4 wc = *(const float4*)&sw1p[oc * 12 + 8];
        const float w[9] = {wa.x, wa.y, wa.z, wa.w, wb.x, wb.y, wb.z, wb.w, wc.x};
        const float bias = sb1[oc];
        float* spb = &sp[s * SS + oc * PS + (y2 + 1) * RS];

        #pragma unroll
        for (int xh = 0; xh < 2; xh++) {
            const int SH = xh * 2;      // e[] column shift: cols start at xh*12
            float a0[14], a1[14];
            #pragma unroll
            for (int i2 = 0; i2 < 14; i2++) { a0[i2] = bias; a1[i2] = bias; }

            #pragma unroll
            for (int r = 0; r < 4; r++) {
                float e[20];
                const float* rp = &sx[s][2 * y2 + r][xh * 12];
                #pragma unroll
                for (int q = 0; q < 5; q++) ((float4*)e)[q] = ((const float4*)rp)[q];
                if (r < 3) {
                    #pragma unroll
                    for (int xx = 0; xx < 14; xx++) {
                        float a = a0[xx];
                        a = fmaf(e[xx + SH],     w[3 * r],     a);
                        a = fmaf(e[xx + SH + 1], w[3 * r + 1], a);
                        a = fmaf(e[xx + SH + 2], w[3 * r + 2], a);
                        a0[xx] = a;
                    }
                }
                if (r >= 1) {
                    #pragma unroll
                    for (int xx = 0; xx < 14; xx++) {
                        float a = a1[xx];
                        a = fmaf(e[xx + SH],     w[3 * (r - 1)],     a);
                        a = fmaf(e[xx + SH + 1], w[3 * (r - 1) + 1], a);
                        a = fmaf(e[xx + SH + 2], w[3 * (r - 1) + 2], a);
                        a1[xx] = a;
                    }
                }
            }
            #pragma unroll
            for (int p = 0; p < 7; p++) {
                float a = fmaxf(a0[2 * p], 0.0f);
                a = fmaxf(a, fmaxf(a0[2 * p + 1], 0.0f));
                a = fmaxf(a, fmaxf(a1[2 * p], 0.0f));
                a = fmaxf(a, fmaxf(a1[2 * p + 1], 0.0f));
                spb[xh * 7 + p + 1] = a;
            }
        }
    }
    __syncthreads();

    // -------- conv2 (8->16) + relu + pool -> sflat -> g_flat --------
    {
        const int oc = tid & 15;
        const int rest = tid >> 4;     // 0..13
        const int y2 = rest % 7;
        const int s = rest / 7;
        const float bias = sb2[oc];
        float acc0[14], acc1[14];
        #pragma unroll
        for (int i2 = 0; i2 < 14; i2++) { acc0[i2] = bias; acc1[i2] = bias; }

        #pragma unroll
        for (int ic = 0; ic < 8; ic++) {
            const float* wp = &sw2p[oc * 100 + ic * 12];
            float4 wa = *(const float4*)(wp);
            float4 wb = *(const float4*)(wp + 4);
            float4 wc = *(const float4*)(wp + 8);
            const float w[9] = {wa.x, wa.y, wa.z, wa.w, wb.x, wb.y, wb.z, wb.w, wc.x};

            const float* rowp = &sp[s * SS + ic * PS + (2 * y2) * RS];
            #pragma unroll
            for (int r = 0; r < 4; r++) {
                float e[16];
                #pragma unroll
                for (int q = 0; q < 4; q++)
                    ((float4*)e)[q] = ((const float4*)(rowp + r * RS))[q];
                if (r < 3) {
                    #pragma unroll
                    for (int xx = 0; xx < 14; xx++) {
                        float a = acc0[xx];
                        a = fmaf(e[xx],     w[3 * r],     a);
                        a = fmaf(e[xx + 1], w[3 * r + 1], a);
                        a = fmaf(e[xx + 2], w[3 * r + 2], a);
                        acc0[xx] = a;
                    }
                }
                if (r >= 1) {
                    #pragma unroll
                    for (int xx = 0; xx < 14; xx++) {
                        float a = acc1[xx];
                        a = fmaf(e[xx],     w[3 * (r - 1)],     a);
                        a = fmaf(e[xx + 1], w[3 * (r - 1) + 1], a);
                        a = fmaf(e[xx + 2], w[3 * (r - 1) + 2], a);
                        acc1[xx] = a;
                    }
                }
            }
        }

        float* stg = &sflat[s * 784 + oc * 49 + y2 * 7];
        #pragma unroll
        for (int p = 0; p < 7; p++) {
            float a = fmaxf(acc0[2 * p], 0.0f);
            a = fmaxf(a, fmaxf(acc0[2 * p + 1], 0.0f));
            a = fmaxf(a, fmaxf(acc1[2 * p], 0.0f));
            a = fmaxf(a, fmaxf(acc1[2 * p + 1], 0.0f));
            stg[p] = a;
        }
    }
    __syncthreads();

    // Coalesced write of both samples' flats
    {
        float4* dst = (float4*)&g_flat[b0 * 784];
        const float4* src = (const float4*)sflat;
        for (int i = tid; i < 392; i += 224) dst[i] = src[i];
    }
}

// ---------------------------------------------------------------------------
// K2: FC1(784->64)+relu + FC2(64->4), tiled GEMM. 64 samples/block.
// ---------------------------------------------------------------------------
#define FC_STRIDE 60
__global__ __launch_bounds__(256)
void k_fc(const float* __restrict__ fc1_w, const float* __restrict__ fc1_b,
          const float* __restrict__ fc2_w, const float* __restrict__ fc2_b) {
    __shared__ __align__(16) float sAW[2 * 64 * FC_STRIDE];
    __shared__ float sw2[256];
    float* sA = sAW;
    float* sW = sAW + 64 * FC_STRIDE;

    const int tid = threadIdx.x;
    const int s0 = blockIdx.x * 64;
    const int jj = tid & 31;
    const int ss = tid >> 5;

    for (int i = tid; i < 256; i += 256) sw2[i] = fc2_w[i];

    float acc[2][8];
    #pragma unroll
    for (int u = 0; u < 8; u++) { acc[0][u] = 0.0f; acc[1][u] = 0.0f; }

    for (int kt = 0; kt < 784; kt += 56) {
        __syncthreads();
        #pragma unroll
        for (int i = tid; i < 64 * 14; i += 256) {
            int r = i / 14, q = i % 14;
            ((float4*)&sA[r * FC_STRIDE])[q] =
                *(const float4*)&g_flat[(s0 + r) * 784 + kt + q * 4];
            ((float4*)&sW[r * FC_STRIDE])[q] =
                *(const float4*)&fc1_w[r * 784 + kt + q * 4];
        }
        __syncthreads();
        #pragma unroll
        for (int k4 = 0; k4 < 14; k4++) {
            float4 w0 = *(const float4*)&sW[jj * FC_STRIDE + k4 * 4];
            float4 w1 = *(const float4*)&sW[(jj + 32) * FC_STRIDE + k4 * 4];
            #pragma unroll
            for (int u = 0; u < 8; u++) {
                float4 a = *(const float4*)&sA[(ss * 8 + u) * FC_STRIDE + k4 * 4];
                float t0 = acc[0][u], t1 = acc[1][u];
                t0 = fmaf(a.x, w0.x, t0); t1 = fmaf(a.x, w1.x, t1);
                t0 = fmaf(a.y, w0.y, t0); t1 = fmaf(a.y, w1.y, t1);
                t0 = fmaf(a.z, w0.z, t0); t1 = fmaf(a.z, w1.z, t1);
                t0 = fmaf(a.w, w0.w, t0); t1 = fmaf(a.w, w1.w, t1);
                acc[0][u] = t0; acc[1][u] = t1;
            }
        }
    }

    __syncthreads();
    float* sh = sAW;
    const float bj0 = fc1_b[jj], bj1 = fc1_b[jj + 32];
    #pragma unroll
    for (int u = 0; u < 8; u++) {
        sh[(ss * 8 + u) * 65 + jj]      = fmaxf(acc[0][u] + bj0, 0.0f);
        sh[(ss * 8 + u) * 65 + jj + 32] = fmaxf(acc[1][u] + bj1, 0.0f);
    }
    __syncthreads();

    {
        const int s = tid >> 2, c = tid & 3;
        float a = fc2_b[c];
        const float* hp = &sh[s * 65];
        const float* wc = &sw2[c * 64];
        #pragma unroll
        for (int j = 0; j < 64; j++) a = fmaf(hp[j], wc[j], a);
        g_feat[(s0 + s) * 4 + c] = a;
    }
}

// ---------------------------------------------------------------------------
// K3: batch mean/var -> scale/shift
// ---------------------------------------------------------------------------
__global__ void k_stats(const float* __restrict__ bn_g,
                        const float* __restrict__ bn_b) {
    __shared__ double ss[256][8];
    const int tid = threadIdx.x;
    double sum[4] = {0, 0, 0, 0}, sq[4] = {0, 0, 0, 0};
    for (int s = tid; s < BATCH; s += 256) {
        float4 f = ((const float4*)g_feat)[s];
        double v;
        v = (double)f.x; sum[0] += v; sq[0] += v * v;
        v = (double)f.y; sum[1] += v; sq[1] += v * v;
        v = (double)f.z; sum[2] += v; sq[2] += v * v;
        v = (double)f.w; sum[3] += v; sq[3] += v * v;
    }
    #pragma unroll
    for (int c = 0; c < 4; c++) { ss[tid][c] = sum[c]; ss[tid][4 + c] = sq[c]; }
    __syncthreads();
    for (int off = 128; off >= 1; off >>= 1) {
        if (tid < off) {
            #pragma unroll
            for (int k = 0; k < 8; k++) ss[tid][k] += ss[tid + off][k];
        }
        __syncthreads();
    }
    if (tid < 4) {
        double m = ss[0][tid] / (double)BATCH;
        double var = ss[0][4 + tid] / (double)BATCH - m * m;
        float scale = (float)((double)bn_g[tid] / sqrt(var + 1e-5));
        float shift = bn_b[tid] - (float)m * scale;
        g_scsh[tid] = scale;
        g_scsh[4 + tid] = shift;
    }
}

// ---------------------------------------------------------------------------
// K4: quantum state-vector sim + PauliZ measurement
// ---------------------------------------------------------------------------
template <int STR>
__device__ __forceinline__ void rot_rx(float* sr, float* si, float c, float s) {
    #pragma unroll
    for (int k = 0; k < 16; k++) {
        if (k & STR) continue;
        int k1 = k | STR;
        float ar0 = sr[k], ai0 = si[k], ar1 = sr[k1], ai1 = si[k1];
        sr[k]  = c * ar0 + s * ai1;
        si[k]  = c * ai0 - s * ar1;
        sr[k1] = s * ai0 + c * ar1;
        si[k1] = -s * ar0 + c * ai1;
    }
}

template <int STR>
__device__ __forceinline__ void rot_ry(float* sr, float* si, float c, float s) {
    #pragma unroll
    for (int k = 0; k < 16; k++) {
        if (k & STR) continue;
        int k1 = k | STR;
        float ar0 = sr[k], ai0 = si[k], ar1 = sr[k1], ai1 = si[k1];
        sr[k]  = c * ar0 - s * ar1;
        si[k]  = c * ai0 - s * ai1;
        sr[k1] = s * ar0 + c * ar1;
        si[k1] = s * ai0 + c * ai1;
    }
}

template <int STR>
__device__ __forceinline__ void rot_rz(float* sr, float* si, float c, float s) {
    #pragma unroll
    for (int k = 0; k < 16; k++) {
        float ar = sr[k], ai = si[k];
        if (k & STR) { sr[k] = c * ar - s * ai; si[k] = c * ai + s * ar; }
        else         { sr[k] = c * ar + s * ai; si[k] = c * ai - s * ar; }
    }
}

__device__ __forceinline__ void cnot_c3_t0(float* sr, float* si) {
    #pragma unroll
    for (int k = 1; k < 8; k += 2) {
        int k1 = k | 8;
        float tr = sr[k], ti = si[k];
        sr[k] = sr[k1]; si[k] = si[k1];
        sr[k1] = tr;    si[k1] = ti;
    }
}

__global__ void k_quantum(const float* __restrict__ rl_params,
                          float* __restrict__ out) {
    __shared__ float gc[23], gs[23];
    const int tid = threadIdx.x;
    if (tid < 23) {
        float t = rl_params[tid] * 0.5f;
        gc[tid] = cosf(t);
        gs[tid] = sinf(t);
    }
    __syncthreads();

    const int b = blockIdx.x * blockDim.x + tid;
    if (b >= BATCH) return;

    float sr[16], si[16];
    #pragma unroll
    for (int k = 0; k < 16; k++) { sr[k] = 0.0f; si[k] = 0.0f; }
    sr[0] = 1.0f;

    float4 f4 = ((const float4*)g_feat)[b];
    {
        float f, s, c;
        f = (f4.x * g_scsh[0] + g_scsh[4]) * 0.5f; s = sinf(f); c = cosf(f);
        rot_rx<8>(sr, si, c, s);
        f = (f4.y * g_scsh[1] + g_scsh[5]) * 0.5f; s = sinf(f); c = cosf(f);
        rot_rx<4>(sr, si, c, s);
        f = (f4.z * g_scsh[2] + g_scsh[6]) * 0.5f; s = sinf(f); c = cosf(f);
        rot_rx<2>(sr, si, c, s);
        f = (f4.w * g_scsh[3] + g_scsh[7]) * 0.5f; s = sinf(f); c = cosf(f);
        rot_rx<1>(sr, si, c, s);
    }

    #pragma unroll
    for (int r = 0; r < 7; r++) {
        rot_rx<8>(sr, si, gc[3 * r],     gs[3 * r]);
        rot_ry<4>(sr, si, gc[3 * r + 1], gs[3 * r + 1]);
        rot_rz<2>(sr, si, gc[3 * r + 2], gs[3 * r + 2]);
        cnot_c3_t0(sr, si);
    }
    rot_rx<8>(sr, si, gc[21], gs[21]);
    rot_ry<4>(sr, si, gc[22], gs[22]);

    float p[16];
    #pragma unroll
    for (int k = 0; k < 16; k++) p[k] = sr[k] * sr[k] + si[k] * si[k];
    #pragma unroll
    for (int w = 0; w < 4; w++) {
        int str = 8 >> w;
        float acc = 0.0f;
        #pragma unroll
        for (int k = 0; k < 16; k++) acc += (k & str) ? -p[k] : p[k];
        out[b * 4 + w] = acc;
    }
}

// ---------------------------------------------------------------------------
// Launch (3 dummies first so ncu's profiled launch, index 3, is k_conv)
// ---------------------------------------------------------------------------
extern "C" void kernel_launch(void* const* d_in, const int* in_sizes, int n_in,
                              void* d_out, int out_size) {
    const float* x       = (const float*)d_in[0];
    const float* conv1_w = (const float*)d_in[1];
    const float* conv1_b = (const float*)d_in[2];
    const float* conv2_w = (const float*)d_in[3];
    const float* conv2_b = (const float*)d_in[4];
    const float* fc1_w   = (const float*)d_in[5];
    const float* fc1_b   = (const float*)d_in[6];
    const float* fc2_w   = (const float*)d_in[7];
    const float* fc2_b   = (const float*)d_in[8];
    const float* bn_g    = (const float*)d_in[9];
    const float* bn_b    = (const float*)d_in[10];
    const float* rl      = (const float*)d_in[11];
    float* out = (float*)d_out;

    k_nop<<<1, 32>>>();
    k_nop<<<1, 32>>>();
    k_nop<<<1, 32>>>();
    k_conv<<<BATCH / 2, 224>>>(x, conv1_w, conv1_b, conv2_w, conv2_b);
    k_fc<<<BATCH / 64, 256>>>(fc1_w, fc1_b, fc2_w, fc2_b);
    k_stats<<<1, 256>>>(bn_g, bn_b);
    k_quantum<<<BATCH / 256, 256>>>(rl, out);
}